// round 6
// baseline (speedup 1.0000x reference)
#include <cuda_runtime.h>
#include <math.h>

#define N_NODES 500000
#define N_EDGES 16000000

#define BSH     10                       // bucket = src >> 10
#define BWIN    (1 << BSH)               // 1024 nodes per bucket
#define NBKT    ((N_NODES + BWIN - 1) >> BSH)   // 489
#define CAP     49152                    // per-bucket capacity (mean 32.7K)
#define NSLICE  8                        // blocks per bucket in binned passes
#define EPB     4096                     // edges per scatter block
#define SCB     ((N_EDGES + EPB - 1) / EPB)     // 3907
#define OVF     (1 << 20)

// ---------------- device scratch (no allocation allowed) ----------------
__device__ unsigned long long g_rec2[(size_t)NBKT * CAP]; // s:19|d:19|top26(-w):26
__device__ unsigned long long g_ovf[OVF];
__device__ unsigned int       g_ovf_cnt;
__device__ unsigned int       g_bcur[NBKT];   // absolute write cursors
__device__ float  g_deg[N_NODES];    // degree -> overwritten with dinv
__device__ float2 g_xs[N_NODES];     // dinv * x
__device__ float2 g_t1[N_NODES];     // raw accumulator pass 1
__device__ float2 g_y1[N_NODES];     // dinv * t1 (true Tx1)
__device__ float2 g_g1[N_NODES];     // dinv * y1
__device__ float2 g_t2[N_NODES];     // raw accumulator pass 2
__device__ int    g_is32;

// ---------------- helpers ----------------
__device__ __forceinline__ void red_add_v2(float2* addr, float a, float b) {
    asm volatile("red.global.add.v2.f32 [%0], {%1, %2};"
                 :: "l"(addr), "f"(a), "f"(b) : "memory");
}

__device__ __forceinline__ unsigned long long pack_rec(int s, int d, float w) {
    unsigned int wb = 0u;
    if (w != 0.f) wb = __float_as_uint(-w);
    return (unsigned long long)(unsigned)s
         | ((unsigned long long)(unsigned)d << 19)
         | ((unsigned long long)(wb >> 6) << 38);
}

__device__ __forceinline__ void spill_rec(unsigned long long rec) {
    unsigned p = atomicAdd(&g_ovf_cnt, 1u);
    if (p < OVF) g_ovf[p] = rec;
}

// ---------------- kernels ----------------
__global__ void k_initcur() {
    int i = blockIdx.x * blockDim.x + threadIdx.x;
    if (i < NBKT) g_bcur[i] = (unsigned)(i * CAP);
    if (i == 0) g_ovf_cnt = 0u;
}

__global__ void k_detect(const int* ei32) {
    if (threadIdx.x == 0) g_is32 = 0;
    __syncthreads();
    int found = 0;
    for (int k = threadIdx.x; k < 4000; k += 256) {
        if (ei32[(size_t)k * 7800 + 1] != 0) { found = 1; break; }
    }
    if (found) atomicOr(&g_is32, 1);
}

// Counting-sort scatter. Ranks captured from the phase-1 histogram atomics,
// so the permutation is built with plain stores (no second atomic pass).
__global__ void k_scatter(const void* __restrict__ ei, const float* __restrict__ ew) {
    __shared__ unsigned int sh_hist[512];
    __shared__ unsigned int sh_excl[512];
    __shared__ unsigned int sh_scan[256];
    __shared__ int          sh_delta[512];
    __shared__ unsigned long long sh_stage[EPB];
    __shared__ unsigned short     sh_inv[EPB];

    const int tid = threadIdx.x;
    const int base = blockIdx.x * EPB;
    const int is32 = g_is32;

    for (int i = tid; i < 512; i += 256) sh_hist[i] = 0u;
    __syncthreads();

    // Phase 1: one vectorized read; pack; histogram with rank capture.
    unsigned short rank[16];
    #pragma unroll
    for (int k = 0; k < EPB / 1024; k++) {
        int e0 = base + k * 1024 + tid * 4;
        int li = k * 1024 + tid * 4;
        if (e0 + 3 < N_EDGES) {
            int s[4], d[4];
            if (is32) {
                int4 sv = __ldg((const int4*)((const int*)ei + e0));
                int4 dv = __ldg((const int4*)((const int*)ei + N_EDGES + e0));
                s[0]=sv.x; s[1]=sv.y; s[2]=sv.z; s[3]=sv.w;
                d[0]=dv.x; d[1]=dv.y; d[2]=dv.z; d[3]=dv.w;
            } else {
                const long long* p = (const long long*)ei;
                longlong2 a = __ldg((const longlong2*)(p + e0));
                longlong2 b = __ldg((const longlong2*)(p + e0 + 2));
                longlong2 c = __ldg((const longlong2*)(p + N_EDGES + e0));
                longlong2 f = __ldg((const longlong2*)(p + N_EDGES + e0 + 2));
                s[0]=(int)a.x; s[1]=(int)a.y; s[2]=(int)b.x; s[3]=(int)b.y;
                d[0]=(int)c.x; d[1]=(int)c.y; d[2]=(int)f.x; d[3]=(int)f.y;
            }
            float4 wv = __ldg((const float4*)(ew + e0));
            float w[4] = {wv.x, wv.y, wv.z, wv.w};
            #pragma unroll
            for (int j = 0; j < 4; j++) {
                float wm = (s[j] == d[j]) ? 0.f : w[j];
                sh_stage[li + j] = pack_rec(s[j], d[j], wm);
                rank[k * 4 + j] = (unsigned short)atomicAdd(&sh_hist[s[j] >> BSH], 1u);
            }
        } else {
            #pragma unroll
            for (int j = 0; j < 4; j++) {
                int e = e0 + j;
                if (e < N_EDGES) {
                    int s = is32 ? __ldg((const int*)ei + e)
                                 : (int)__ldg((const long long*)ei + e);
                    int d = is32 ? __ldg((const int*)ei + N_EDGES + e)
                                 : (int)__ldg((const long long*)ei + N_EDGES + e);
                    float w = __ldg(ew + e);
                    if (s == d) w = 0.f;
                    sh_stage[li + j] = pack_rec(s, d, w);
                    rank[k * 4 + j] = (unsigned short)atomicAdd(&sh_hist[s >> BSH], 1u);
                }
            }
        }
    }
    __syncthreads();

    // Phase 2: exclusive scan over 512 buckets (2 per thread).
    unsigned a0 = sh_hist[2 * tid], a1 = sh_hist[2 * tid + 1];
    sh_scan[tid] = a0 + a1;
    __syncthreads();
    for (int off = 1; off < 256; off <<= 1) {
        unsigned v = sh_scan[tid];
        unsigned add = (tid >= off) ? sh_scan[tid - off] : 0u;
        __syncthreads();
        sh_scan[tid] = v + add;
        __syncthreads();
    }
    unsigned total = sh_scan[255];
    unsigned excl = (tid == 0) ? 0u : sh_scan[tid - 1];

    // Phase 3: publish exclusive offsets; reserve global space.
    int b0 = 2 * tid, b1 = 2 * tid + 1;
    sh_excl[b0] = excl;
    sh_excl[b1] = excl + a0;
    if (a0) { unsigned g = atomicAdd(&g_bcur[b0], a0); sh_delta[b0] = (int)g - (int)excl; }
    if (a1) { unsigned g = atomicAdd(&g_bcur[b1], a1); sh_delta[b1] = (int)g - (int)(excl + a0); }
    __syncthreads();

    // Phase 4: build inverse permutation with plain stores (no atomics).
    #pragma unroll
    for (int k = 0; k < EPB / 1024; k++) {
        int li = k * 1024 + tid * 4;
        #pragma unroll
        for (int j = 0; j < 4; j++) {
            int e = base + li + j;
            if (e < N_EDGES) {
                unsigned long long rec = sh_stage[li + j];
                int b = (int)((rec >> BSH) & 0x1FFu);
                sh_inv[sh_excl[b] + rank[k * 4 + j]] = (unsigned short)(li + j);
            }
        }
    }
    __syncthreads();

    // Phase 5: ordered coalesced write-out (streaming stores).
    for (unsigned p = tid; p < total; p += 256) {
        unsigned long long rec = sh_stage[sh_inv[p]];
        int b = (int)((rec >> BSH) & 0x1FFu);
        unsigned gpos = (unsigned)((int)p + sh_delta[b]);
        if (gpos < (unsigned)(b + 1) * CAP) __stcs(&g_rec2[gpos], rec);
        else spill_rec(rec);
    }
}

// Degree: smem window per bucket, vectorized streaming record reads.
__global__ void k_deg2() {
    __shared__ float sh[BWIN];
    const int tid = threadIdx.x;
    const int b = blockIdx.x / NSLICE;
    const int j = blockIdx.x % NSLICE;
    unsigned cnt = g_bcur[b] - (unsigned)(b * CAP);
    if (cnt > CAP) cnt = CAP;
    unsigned chunk = (((cnt + NSLICE - 1) / NSLICE) + 1u) & ~1u;
    unsigned s0 = min(cnt, j * chunk), s1 = min(cnt, s0 + chunk);

    for (int i = tid; i < BWIN; i += 256) sh[i] = 0.f;
    __syncthreads();

    const unsigned long long* base = &g_rec2[(size_t)b * CAP];
    unsigned i = s0 + 2u * tid;
    for (; i + 1 < s1; i += 512) {
        longlong2 v = __ldcs((const longlong2*)(base + i));
        unsigned long long r0 = (unsigned long long)v.x, r1 = (unsigned long long)v.y;
        unsigned w0 = (unsigned)(r0 >> 38) << 6;
        unsigned w1 = (unsigned)(r1 >> 38) << 6;
        if (w0) atomicAdd(&sh[(unsigned)(r0 & 0x3FFu)], -__uint_as_float(w0));
        if (w1) atomicAdd(&sh[(unsigned)(r1 & 0x3FFu)], -__uint_as_float(w1));
    }
    if (i < s1) {
        unsigned long long r0 = __ldcs((const long long*)(base + i));
        unsigned w0 = (unsigned)(r0 >> 38) << 6;
        if (w0) atomicAdd(&sh[(unsigned)(r0 & 0x3FFu)], -__uint_as_float(w0));
    }
    __syncthreads();
    for (int k = tid; k < BWIN; k += 256) {
        float v = sh[k];
        int node = (b << BSH) + k;
        if (v != 0.f && node < N_NODES) atomicAdd(&g_deg[node], v);
    }
    if (blockIdx.x == gridDim.x - 1) {
        unsigned n = g_ovf_cnt; if (n > OVF) n = OVF;
        for (unsigned q = tid; q < n; q += 256) {
            unsigned long long rec = g_ovf[q];
            unsigned wb = (unsigned)(rec >> 38) << 6;
            if (wb) atomicAdd(&g_deg[rec & 0x7FFFFu], -__uint_as_float(wb));
        }
    }
}

// dinv = rsqrt(deg); xs = dinv * x
__global__ void k_dinv(const float4* __restrict__ x) {
    int t = blockIdx.x * blockDim.x + threadIdx.x;
    int i = t * 2;
    if (i >= N_NODES) return;
    float2 dg = *(const float2*)&g_deg[i];
    float d0 = (dg.x > 0.f) ? rsqrtf(dg.x) : 0.f;
    float d1 = (dg.y > 0.f) ? rsqrtf(dg.y) : 0.f;
    *(float2*)&g_deg[i] = make_float2(d0, d1);
    float4 xv = __ldg(&x[t]);
    *(float4*)&g_xs[i] = make_float4(d0 * xv.x, d0 * xv.y, d1 * xv.z, d1 * xv.w);
}

// Prop pass: bucket's source window staged in smem (8 KB); reds to L2.
template <bool PASS1>
__global__ void k_prop() {
    __shared__ float2 sh_v[BWIN];
    const int tid = threadIdx.x;
    const int b = blockIdx.x / NSLICE;
    const int j = blockIdx.x % NSLICE;
    const int nbase = b << BSH;

    const float2* src = PASS1 ? g_xs : g_g1;
    float2* dst = PASS1 ? g_t1 : g_t2;

    for (int i = tid; i < BWIN; i += 256) {
        int node = nbase + i;
        sh_v[i] = (node < N_NODES) ? src[node] : make_float2(0.f, 0.f);
    }
    __syncthreads();

    unsigned cnt = g_bcur[b] - (unsigned)(b * CAP);
    if (cnt > CAP) cnt = CAP;
    unsigned chunk = (((cnt + NSLICE - 1) / NSLICE) + 1u) & ~1u;
    unsigned s0 = min(cnt, j * chunk), s1 = min(cnt, s0 + chunk);
    const unsigned long long* base = &g_rec2[(size_t)b * CAP];

    unsigned i = s0 + 2u * tid;
    for (; i + 1 < s1; i += 512) {
        longlong2 v = __ldcs((const longlong2*)(base + i));
        unsigned long long r0 = (unsigned long long)v.x, r1 = (unsigned long long)v.y;
        unsigned w0 = (unsigned)(r0 >> 38) << 6;
        unsigned w1 = (unsigned)(r1 >> 38) << 6;
        if (w0) {
            float2 xv = sh_v[(unsigned)(r0 & 0x3FFu)];
            float nw = __uint_as_float(w0);
            red_add_v2(&dst[(r0 >> 19) & 0x7FFFFu], nw * xv.x, nw * xv.y);
        }
        if (w1) {
            float2 xv = sh_v[(unsigned)(r1 & 0x3FFu)];
            float nw = __uint_as_float(w1);
            red_add_v2(&dst[(r1 >> 19) & 0x7FFFFu], nw * xv.x, nw * xv.y);
        }
    }
    if (i < s1) {
        unsigned long long r0 = __ldcs((const long long*)(base + i));
        unsigned w0 = (unsigned)(r0 >> 38) << 6;
        if (w0) {
            float2 xv = sh_v[(unsigned)(r0 & 0x3FFu)];
            float nw = __uint_as_float(w0);
            red_add_v2(&dst[(r0 >> 19) & 0x7FFFFu], nw * xv.x, nw * xv.y);
        }
    }

    if (blockIdx.x == gridDim.x - 1) {
        unsigned n = g_ovf_cnt; if (n > OVF) n = OVF;
        for (unsigned q = tid; q < n; q += 256) {
            unsigned long long rec = g_ovf[q];
            unsigned wb = (unsigned)(rec >> 38) << 6;
            if (wb) {
                int s = (int)(rec & 0x7FFFFu);
                float2 xv = __ldg(&src[s]);
                float nw = __uint_as_float(wb);
                red_add_v2(&dst[(rec >> 19) & 0x7FFFFu], nw * xv.x, nw * xv.y);
            }
        }
    }
}

__global__ void k_scale2() {
    int t = blockIdx.x * blockDim.x + threadIdx.x;
    int i = t * 2;
    if (i >= N_NODES) return;
    float2 di = *(const float2*)&g_deg[i];
    float4 t1 = *(const float4*)&g_t1[i];
    float4 y1 = make_float4(di.x * t1.x, di.x * t1.y, di.y * t1.z, di.y * t1.w);
    *(float4*)&g_y1[i] = y1;
    *(float4*)&g_g1[i] = make_float4(di.x * y1.x, di.x * y1.y, di.y * y1.z, di.y * y1.w);
}

__global__ void k_final(const float2* __restrict__ x,
                        const float* __restrict__ Wz,
                        const float* __restrict__ Wh,
                        const float* __restrict__ bxz,
                        const float* __restrict__ bhz,
                        const float* __restrict__ bxh,
                        const float* __restrict__ bhh,
                        float* __restrict__ out) {
    int i = blockIdx.x * blockDim.x + threadIdx.x;
    if (i >= N_NODES) return;
    float di = g_deg[i];
    float2 T0 = __ldg(&x[i]);
    float2 T1 = g_y1[i];
    float2 t2 = g_t2[i];
    float T2x = 2.f * (di * t2.x) - T0.x;
    float T2y = 2.f * (di * t2.y) - T0.y;

    float Az = T0.x * __ldg(Wz + 0) + T0.y * __ldg(Wz + 1)
             + T1.x * __ldg(Wz + 2) + T1.y * __ldg(Wz + 3)
             + T2x  * __ldg(Wz + 4) + T2y  * __ldg(Wz + 5)
             + __ldg(bxz) + __ldg(bhz);
    float Ah = T0.x * __ldg(Wh + 0) + T0.y * __ldg(Wh + 1)
             + T1.x * __ldg(Wh + 2) + T1.y * __ldg(Wh + 3)
             + T2x  * __ldg(Wh + 4) + T2y  * __ldg(Wh + 5)
             + __ldg(bxh) + __ldg(bhh);

    float z = 1.f / (1.f + expf(-Az));
    out[i] = (1.f - z) * tanhf(Ah);
}

// ---------------- host ----------------
extern "C" void kernel_launch(void* const* d_in, const int* in_sizes, int n_in,
                              void* d_out, int out_size) {
    const float* x  = (const float*)d_in[0];
    const void*  ei = d_in[1];
    const float* ew = (const float*)d_in[2];

    int iWxz = 3, iWxh = 5, ibxz = 9, ibhz = 10, ibxh = 13, ibhh = 14; // dict order
    if (n_in >= 15 && in_sizes[4] == 1) { // signature order
        iWxz = 3; ibxz = 4; ibhz = 6; iWxh = 11; ibxh = 12; ibhh = 14;
    }
    const float* Wz  = (const float*)d_in[iWxz];
    const float* Wh  = (const float*)d_in[iWxh];
    const float* bxz = (const float*)d_in[ibxz];
    const float* bhz = (const float*)d_in[ibhz];
    const float* bxh = (const float*)d_in[ibxh];
    const float* bhh = (const float*)d_in[ibhh];

    const int TPB = 256;
    const int NB  = (N_NODES + TPB - 1) / TPB;
    const int NB2 = (N_NODES / 2 + TPB - 1) / TPB;

    void *p_deg, *p_t1, *p_t2;
    cudaGetSymbolAddress(&p_deg, g_deg);
    cudaGetSymbolAddress(&p_t1,  g_t1);
    cudaGetSymbolAddress(&p_t2,  g_t2);
    cudaMemsetAsync(p_deg, 0, N_NODES * sizeof(float), 0);
    cudaMemsetAsync(p_t1,  0, N_NODES * sizeof(float2), 0);
    cudaMemsetAsync(p_t2,  0, N_NODES * sizeof(float2), 0);

    k_initcur<<<(NBKT + TPB - 1) / TPB, TPB>>>();
    k_detect<<<1, 256>>>((const int*)ei);
    k_scatter<<<SCB, TPB>>>(ei, ew);
    k_deg2<<<NBKT * NSLICE, TPB>>>();
    k_dinv<<<NB2, TPB>>>((const float4*)x);
    k_prop<true><<<NBKT * NSLICE, TPB>>>();
    k_scale2<<<NB2, TPB>>>();
    k_prop<false><<<NBKT * NSLICE, TPB>>>();
    k_final<<<NB, TPB>>>((const float2*)x, Wz, Wh, bxz, bhz, bxh, bhh,
                         (float*)d_out);
}